// round 16
// baseline (speedup 1.0000x reference)
#include <cuda_runtime.h>
#include <cuda_bf16.h>
#include <math_constants.h>
#include <cstdint>

// Problem constants (fixed by the reference setup)
#define SEQ    2048
#define DMODEL 1024
#define NHEADS 16
#define DEPTH  64
#define BATCH  2
#define MROWS  (BATCH * SEQ)   // 4096

// Scratch (allocation-free rule: __device__ globals). All bf16 hi/lo pairs.
// Weights stored [K][N] (NO transpose) — GEMM uses ldmatrix.trans for B-frags.
__device__ __nv_bfloat16 g_ah[MROWS * DMODEL];   // x split, later attn split
__device__ __nv_bfloat16 g_al[MROWS * DMODEL];
__device__ __nv_bfloat16 g_yh[MROWS * DMODEL];
__device__ __nv_bfloat16 g_yl[MROWS * DMODEL];
__device__ __nv_bfloat16 g_qh[MROWS * DMODEL];
__device__ __nv_bfloat16 g_ql[MROWS * DMODEL];
__device__ __nv_bfloat16 g_kh[MROWS * DMODEL];
__device__ __nv_bfloat16 g_kl[MROWS * DMODEL];
__device__ __nv_bfloat16 g_vh[MROWS * DMODEL];
__device__ __nv_bfloat16 g_vl[MROWS * DMODEL];
__device__ __nv_bfloat16 g_wqh[DMODEL * DMODEL];
__device__ __nv_bfloat16 g_wql[DMODEL * DMODEL];
__device__ __nv_bfloat16 g_wkh[DMODEL * DMODEL];
__device__ __nv_bfloat16 g_wkl[DMODEL * DMODEL];
__device__ __nv_bfloat16 g_wvh[DMODEL * DMODEL];
__device__ __nv_bfloat16 g_wvl[DMODEL * DMODEL];
__device__ __nv_bfloat16 g_woh[DMODEL * DMODEL];
__device__ __nv_bfloat16 g_wol[DMODEL * DMODEL];
__device__ int g_bias_nonzero;

// ---------------------------------------------------------------------------
// Helpers
// ---------------------------------------------------------------------------
__device__ __forceinline__ void mma_bf16(float* c, const uint32_t* a, const uint32_t* b) {
    asm volatile(
        "mma.sync.aligned.m16n8k16.row.col.f32.bf16.bf16.f32 "
        "{%0,%1,%2,%3}, {%4,%5,%6,%7}, {%8,%9}, {%0,%1,%2,%3};"
        : "+f"(c[0]), "+f"(c[1]), "+f"(c[2]), "+f"(c[3])
        : "r"(a[0]), "r"(a[1]), "r"(a[2]), "r"(a[3]), "r"(b[0]), "r"(b[1]));
}

__device__ __forceinline__ void ldsm_x4(uint32_t& r0, uint32_t& r1, uint32_t& r2,
                                        uint32_t& r3, uint32_t addr) {
    asm volatile("ldmatrix.sync.aligned.m8n8.x4.shared.b16 {%0,%1,%2,%3}, [%4];"
        : "=r"(r0), "=r"(r1), "=r"(r2), "=r"(r3) : "r"(addr));
}

__device__ __forceinline__ void ldsm_x4_t(uint32_t& r0, uint32_t& r1, uint32_t& r2,
                                          uint32_t& r3, uint32_t addr) {
    asm volatile("ldmatrix.sync.aligned.m8n8.x4.trans.shared.b16 {%0,%1,%2,%3}, [%4];"
        : "=r"(r0), "=r"(r1), "=r"(r2), "=r"(r3) : "r"(addr));
}

__device__ __forceinline__ uint32_t smem_u32(const void* p) {
    uint32_t a;
    asm("{ .reg .u64 t; cvta.to.shared.u64 t, %1; cvt.u32.u64 %0, t; }" : "=r"(a) : "l"(p));
    return a;
}

#define CP_ASYNC16(dst, src) \
    asm volatile("cp.async.cg.shared.global [%0], [%1], 16;" :: "r"(dst), "l"(src))
#define CP_COMMIT() asm volatile("cp.async.commit_group;" ::: "memory")
#define CP_WAIT0()  asm volatile("cp.async.wait_group 0;" ::: "memory")
#define CP_WAIT1()  asm volatile("cp.async.wait_group 1;" ::: "memory")

__device__ __forceinline__ void split_bf16(float v, __nv_bfloat16& h, __nv_bfloat16& l) {
    h = __float2bfloat16(v);
    l = __float2bfloat16(v - __bfloat162float(h));
}

// Truncation split of a float pair: hi = top-16-bit bf16s packed via prmt;
// lo = (v - hi) rounded to bf16 pair. h+l == v to ~2^-17.
__device__ __forceinline__ void split_pair_trunc(float v0, float v1,
                                                 uint32_t& hp, uint32_t& lp) {
    uint32_t b0 = __float_as_uint(v0), b1 = __float_as_uint(v1);
    asm("prmt.b32 %0, %1, %2, 0x7632;" : "=r"(hp) : "r"(b0), "r"(b1));
    float l0 = v0 - __uint_as_float(b0 & 0xFFFF0000u);
    float l1 = v1 - __uint_as_float(b1 & 0xFFFF0000u);
    asm("cvt.rn.bf16x2.f32 %0, %1, %2;" : "=r"(lp) : "f"(l1), "f"(l0));
}

// ---------------------------------------------------------------------------
// Bias zero-detection (correct for arbitrary bias; fast path when all-zero)
// ---------------------------------------------------------------------------
__global__ void reset_flag_kernel() { g_bias_nonzero = 0; }

__global__ __launch_bounds__(256) void bias_check_kernel(
    const float* __restrict__ bias, int n4)
{
    int i = blockIdx.x * blockDim.x + threadIdx.x;
    int stride = gridDim.x * blockDim.x;
    int local = 0;
    for (; i < n4; i += stride) {
        float4 v = ((const float4*)bias)[i];
        if (v.x != 0.f || v.y != 0.f || v.z != 0.f || v.w != 0.f) { local = 1; break; }
    }
    if (__syncthreads_or(local))
        if (threadIdx.x == 0) atomicOr(&g_bias_nonzero, 1);
}

// ---------------------------------------------------------------------------
// Batched elementwise hi/lo split: x, y, and the 4 weights (no transpose).
// ---------------------------------------------------------------------------
struct SplitBatch {
    const float* in[6];
    __nv_bfloat16 *oh[6], *ol[6];
    int n4[6];
};

__global__ __launch_bounds__(256) void split_kernel(SplitBatch sb)
{
    const int z = blockIdx.z;
    int i = blockIdx.x * blockDim.x + threadIdx.x;
    if (i >= sb.n4[z]) return;
    float4 v = ((const float4*)sb.in[z])[i];
    __nv_bfloat16 h0, h1, h2, h3, l0, l1, l2, l3;
    split_bf16(v.x, h0, l0); split_bf16(v.y, h1, l1);
    split_bf16(v.z, h2, l2); split_bf16(v.w, h3, l3);
    __nv_bfloat162* ph = (__nv_bfloat162*)sb.oh[z];
    __nv_bfloat162* pl = (__nv_bfloat162*)sb.ol[z];
    ph[i * 2 + 0] = __halves2bfloat162(h0, h1);
    ph[i * 2 + 1] = __halves2bfloat162(h2, h3);
    pl[i * 2 + 0] = __halves2bfloat162(l0, l1);
    pl[i * 2 + 1] = __halves2bfloat162(l2, l3);
}

// ---------------------------------------------------------------------------
// 3-term bf16 GEMM body: A [M][K] row-major, W [K][N] row-major.
// cp.async double-buffered, ldmatrix frags, RAW-chain-free MMA ordering.
// CTA tile 128x128, K chunk 32, 8 warps, warp tile 32x64.
// ---------------------------------------------------------------------------
#define GSTRIDE 56
#define WSTRIDE 136                             // W tile row stride (u16): trans-LDSM conflict-free
#define ATILE_B (128 * GSTRIDE * 2)             // 14336 bytes
#define WTILE_B (32 * WSTRIDE * 2)              // 8704 bytes
#define GSTAGE_B (2 * ATILE_B + 2 * WTILE_B)    // 46080
#define GEMM_SMEM (2 * GSTAGE_B)                // 92160

template<int BFOUT>
__device__ __forceinline__ void gemm_body(
    const __nv_bfloat16* __restrict__ Ah, const __nv_bfloat16* __restrict__ Al,
    const __nv_bfloat16* __restrict__ Wh, const __nv_bfloat16* __restrict__ Wl,
    float* __restrict__ C, __nv_bfloat16* __restrict__ Ch,
    __nv_bfloat16* __restrict__ Cl, float alpha, char* gsm)
{
    const uint32_t smb = smem_u32(gsm);
    const int tid  = threadIdx.x;
    const int lane = tid & 31;
    const int wid  = tid >> 5;
    const int g    = lane >> 2;
    const int tig  = lane & 3;
    const int sec  = lane >> 3;
    const int rowin = lane & 7;
    const int wrow = (wid & 3) * 32;
    const int wcol = (wid >> 2) * 64;

    const int blockRow = blockIdx.y * 128;
    const int blockCol = blockIdx.x * 128;
    const int K = DMODEL;

    const uint32_t lane_a = (uint32_t)(((sec & 1) * 8 + rowin) * GSTRIDE + (sec >> 1) * 8);
    const uint32_t lane_w = (uint32_t)(((sec & 1) * 8 + rowin) * WSTRIDE + (sec >> 1) * 8);

    float acc[2][8][4];
    #pragma unroll
    for (int mu = 0; mu < 2; mu++)
        #pragma unroll
        for (int nf = 0; nf < 8; nf++)
            #pragma unroll
            for (int r = 0; r < 4; r++) acc[mu][nf][r] = 0.0f;

    auto issue_load = [&](int k0, int buf) {
        const uint32_t sb = smb + buf * GSTAGE_B;
        #pragma unroll
        for (int j = 0; j < 2; j++) {
            int idx = tid + j * 256;
            int arow = idx >> 2;
            int aseg = idx & 3;
            uint32_t asoff = (uint32_t)(arow * GSTRIDE + aseg * 8) * 2;
            size_t agoff = (size_t)(blockRow + arow) * K + k0 + aseg * 8;
            CP_ASYNC16(sb + asoff,           Ah + agoff);
            CP_ASYNC16(sb + ATILE_B + asoff, Al + agoff);
            int wrow_ = idx >> 4;
            int wseg  = idx & 15;
            uint32_t wsoff = (uint32_t)(wrow_ * WSTRIDE + wseg * 8) * 2;
            size_t wgoff = (size_t)(k0 + wrow_) * DMODEL + blockCol + wseg * 8;
            CP_ASYNC16(sb + 2 * ATILE_B + wsoff,           Wh + wgoff);
            CP_ASYNC16(sb + 2 * ATILE_B + WTILE_B + wsoff, Wl + wgoff);
        }
    };

    issue_load(0, 0);
    CP_COMMIT();

    for (int it = 0; it < 32; it++) {
        if (it + 1 < 32) {
            issue_load((it + 1) * 32, (it + 1) & 1);
            CP_COMMIT();
            CP_WAIT1();
        } else {
            CP_WAIT0();
        }
        __syncthreads();

        const uint32_t sb = smb + (uint32_t)((it & 1) * GSTAGE_B);
        const uint32_t wb = sb + 2 * ATILE_B;

        #pragma unroll
        for (int ks = 0; ks < 2; ks++) {
            const int kb = ks * 16;
            uint32_t ah[2][4], al[2][4];
            #pragma unroll
            for (int mu = 0; mu < 2; mu++) {
                const uint32_t abase = (uint32_t)((wrow + mu * 16) * GSTRIDE + kb) + lane_a;
                ldsm_x4(ah[mu][0], ah[mu][1], ah[mu][2], ah[mu][3], sb + 2 * abase);
                ldsm_x4(al[mu][0], al[mu][1], al[mu][2], al[mu][3], sb + ATILE_B + 2 * abase);
            }
            #pragma unroll
            for (int p = 0; p < 4; p++) {
                const uint32_t wbase = (uint32_t)(kb * WSTRIDE + wcol + p * 16) + lane_w;
                uint32_t bh[4], bl[4];
                ldsm_x4_t(bh[0], bh[1], bh[2], bh[3], wb + 2 * wbase);
                ldsm_x4_t(bl[0], bl[1], bl[2], bl[3], wb + WTILE_B + 2 * wbase);
                // Term-outer ordering: same accumulator revisited only every
                // 4 MMAs (breaks the RAW chain on acc registers).
                mma_bf16(acc[0][2 * p],     ah[0], bh);
                mma_bf16(acc[1][2 * p],     ah[1], bh);
                mma_bf16(acc[0][2 * p + 1], ah[0], bh + 2);
                mma_bf16(acc[1][2 * p + 1], ah[1], bh + 2);
                mma_bf16(acc[0][2 * p],     al[0], bh);
                mma_bf16(acc[1][2 * p],     al[1], bh);
                mma_bf16(acc[0][2 * p + 1], al[0], bh + 2);
                mma_bf16(acc[1][2 * p + 1], al[1], bh + 2);
                mma_bf16(acc[0][2 * p],     ah[0], bl);
                mma_bf16(acc[1][2 * p],     ah[1], bl);
                mma_bf16(acc[0][2 * p + 1], ah[0], bl + 2);
                mma_bf16(acc[1][2 * p + 1], ah[1], bl + 2);
            }
        }
        __syncthreads();
    }

    #pragma unroll
    for (int mu = 0; mu < 2; mu++) {
        #pragma unroll
        for (int nf = 0; nf < 8; nf++) {
            int row0 = blockRow + wrow + mu * 16 + g;
            int col  = blockCol + wcol + nf * 8 + tig * 2;
            float v0 = alpha * acc[mu][nf][0], v1 = alpha * acc[mu][nf][1];
            float v2 = alpha * acc[mu][nf][2], v3 = alpha * acc[mu][nf][3];
            if (BFOUT) {
                __nv_bfloat16 h0, h1, h2, h3, l0, l1, l2, l3;
                split_bf16(v0, h0, l0); split_bf16(v1, h1, l1);
                split_bf16(v2, h2, l2); split_bf16(v3, h3, l3);
                *(__nv_bfloat162*)(Ch + (size_t)row0 * DMODEL + col) = __halves2bfloat162(h0, h1);
                *(__nv_bfloat162*)(Cl + (size_t)row0 * DMODEL + col) = __halves2bfloat162(l0, l1);
                *(__nv_bfloat162*)(Ch + (size_t)(row0 + 8) * DMODEL + col) = __halves2bfloat162(h2, h3);
                *(__nv_bfloat162*)(Cl + (size_t)(row0 + 8) * DMODEL + col) = __halves2bfloat162(l2, l3);
            } else {
                *(float2*)(C + (size_t)row0 * DMODEL + col)       = make_float2(v0, v1);
                *(float2*)(C + (size_t)(row0 + 8) * DMODEL + col) = make_float2(v2, v3);
            }
        }
    }
}

struct GemmBatch {
    const __nv_bfloat16 *Ah[3], *Al[3], *Bh[3], *Bl[3];
    __nv_bfloat16 *Ch[3], *Cl[3];
    float alpha[3];
};

__global__ __launch_bounds__(256, 2) void bf16_gemm_qkv(GemmBatch gb)
{
    extern __shared__ __align__(16) char gsm[];
    const int z = blockIdx.z;
    gemm_body<1>(gb.Ah[z], gb.Al[z], gb.Bh[z], gb.Bl[z],
                 nullptr, gb.Ch[z], gb.Cl[z], gb.alpha[z], gsm);
}

__global__ __launch_bounds__(256, 2) void bf16_gemm_out(
    const __nv_bfloat16* __restrict__ Ah, const __nv_bfloat16* __restrict__ Al,
    const __nv_bfloat16* __restrict__ Bh, const __nv_bfloat16* __restrict__ Bl,
    float* __restrict__ C)
{
    extern __shared__ __align__(16) char gsm[];
    gemm_body<0>(Ah, Al, Bh, Bl, C, nullptr, nullptr, 1.0f, gsm);
}

// ---------------------------------------------------------------------------
// Full-bf16 flash attention v6: v5 with RAW-chain-free MMA ordering.
// ---------------------------------------------------------------------------
#define KS  72
#define VT  72
#define FL_KH 0
#define FL_KL (64 * KS)
#define FL_VH (2 * 64 * KS)
#define FL_VL (2 * 64 * KS + 64 * VT)
#define FL_STAGE (2 * 64 * KS + 2 * 64 * VT)       // 18432 u16 per stage
#define FLASH_SMEM_BYTES (2 * FL_STAGE * 2)        // 73728

__global__ __launch_bounds__(256, 2) void flash_bf16_kernel(
    const __nv_bfloat16* __restrict__ Qh, const __nv_bfloat16* __restrict__ Ql,
    const __nv_bfloat16* __restrict__ Kg_h, const __nv_bfloat16* __restrict__ Kg_l,
    const __nv_bfloat16* __restrict__ Vg_h, const __nv_bfloat16* __restrict__ Vg_l,
    const float* __restrict__ bias,
    __nv_bfloat16* __restrict__ Oh, __nv_bfloat16* __restrict__ Ol)
{
    extern __shared__ uint16_t fsm[];
    const uint32_t smb = smem_u32(fsm);

    const int tid  = threadIdx.x;
    const int lane = tid & 31;
    const int wid  = tid >> 5;
    const int g    = lane >> 2;
    const int tig  = lane & 3;
    const int sec  = lane >> 3;
    const int rowin = lane & 7;

    const int h = blockIdx.y;
    const int b = blockIdx.z;
    const int qbase = blockIdx.x * 128;
    const int wrow  = wid * 16;

    const int bias_on = g_bias_nonzero;

    const uint32_t lane_k = (uint32_t)(((sec >> 1) * 8 + rowin) * KS + (sec & 1) * 8);
    const uint32_t lane_v = (uint32_t)(((sec & 1) * 8 + rowin) * VT + (sec >> 1) * 8);

    uint32_t qfh[4][4], qfl[4][4];
    {
        const uint16_t* qhp = (const uint16_t*)Qh + (size_t)(b * SEQ + qbase + wrow) * DMODEL + h * DEPTH;
        const uint16_t* qlp = (const uint16_t*)Ql + (size_t)(b * SEQ + qbase + wrow) * DMODEL + h * DEPTH;
        #pragma unroll
        for (int ks = 0; ks < 4; ks++) {
            const int c0 = ks * 16 + 2 * tig;
            qfh[ks][0] = *(const uint32_t*)(qhp + (size_t)g * DMODEL + c0);
            qfh[ks][1] = *(const uint32_t*)(qhp + (size_t)(g + 8) * DMODEL + c0);
            qfh[ks][2] = *(const uint32_t*)(qhp + (size_t)g * DMODEL + c0 + 8);
            qfh[ks][3] = *(const uint32_t*)(qhp + (size_t)(g + 8) * DMODEL + c0 + 8);
            qfl[ks][0] = *(const uint32_t*)(qlp + (size_t)g * DMODEL + c0);
            qfl[ks][1] = *(const uint32_t*)(qlp + (size_t)(g + 8) * DMODEL + c0);
            qfl[ks][2] = *(const uint32_t*)(qlp + (size_t)g * DMODEL + c0 + 8);
            qfl[ks][3] = *(const uint32_t*)(qlp + (size_t)(g + 8) * DMODEL + c0 + 8);
        }
    }

    float o[8][4];
    #pragma unroll
    for (int nf = 0; nf < 8; nf++)
        #pragma unroll
        for (int r = 0; r < 4; r++) o[nf][r] = 0.0f;
    float m0 = -CUDART_INF_F, m1 = -CUDART_INF_F, l0 = 0.f, l1 = 0.f;

    const float* bp0 = bias + (size_t)(qbase + wrow + g) * SEQ;
    const float* bp8 = bias + (size_t)(qbase + wrow + g + 8) * SEQ;

    auto load_kv = [&](int kt, int buf) {
        const uint32_t sb = smb + (uint32_t)(buf * FL_STAGE) * 2;
        #pragma unroll
        for (int j = 0; j < 2; j++) {
            int idx = tid + j * 256;
            int row = idx >> 3;
            int seg = idx & 7;
            size_t src = (size_t)(b * SEQ + kt + row) * DMODEL + h * DEPTH + seg * 8;
            uint32_t soff = (uint32_t)(row * KS + seg * 8) * 2;
            CP_ASYNC16(sb + 2 * FL_KH + soff, (const uint16_t*)Kg_h + src);
            CP_ASYNC16(sb + 2 * FL_KL + soff, (const uint16_t*)Kg_l + src);
            CP_ASYNC16(sb + 2 * FL_VH + soff, (const uint16_t*)Vg_h + src);
            CP_ASYNC16(sb + 2 * FL_VL + soff, (const uint16_t*)Vg_l + src);
        }
    };

    load_kv(0, 0);
    CP_COMMIT();

    const int NIT = SEQ / 64;
    for (int it = 0; it < NIT; it++) {
        const int kt = it * 64;
        if (it + 1 < NIT) {
            load_kv(kt + 64, (it + 1) & 1);
            CP_COMMIT();
            CP_WAIT1();
        } else {
            CP_WAIT0();
        }
        __syncthreads();

        const uint32_t sb = smb + (uint32_t)((it & 1) * FL_STAGE) * 2;

        float s[8][4];
        #pragma unroll
        for (int nf = 0; nf < 8; nf++)
            #pragma unroll
            for (int r = 0; r < 4; r++) s[nf][r] = 0.0f;

        #pragma unroll
        for (int ks = 0; ks < 4; ks++) {
            #pragma unroll
            for (int p = 0; p < 4; p++) {
                const uint32_t off = lane_k + (uint32_t)(p * 16 * KS + ks * 16);
                uint32_t bh[4], bl[4];
                ldsm_x4(bh[0], bh[1], bh[2], bh[3], sb + 2 * (FL_KH + off));
                ldsm_x4(bl[0], bl[1], bl[2], bl[3], sb + 2 * (FL_KL + off));
                // Pair-interleaved: s[2p] / s[2p+1] alternate (spacing 2)
                mma_bf16(s[2 * p],     qfh[ks], bh);
                mma_bf16(s[2 * p + 1], qfh[ks], bh + 2);
                mma_bf16(s[2 * p],     qfl[ks], bh);
                mma_bf16(s[2 * p + 1], qfl[ks], bh + 2);
                mma_bf16(s[2 * p],     qfh[ks], bl);
                mma_bf16(s[2 * p + 1], qfh[ks], bl + 2);
            }
        }

        float mx0 = -CUDART_INF_F, mx1 = -CUDART_INF_F;
        if (bias_on) {
            #pragma unroll
            for (int nf = 0; nf < 8; nf++) {
                float2 b0 = *(const float2*)(bp0 + kt + nf * 8 + tig * 2);
                float2 b1 = *(const float2*)(bp8 + kt + nf * 8 + tig * 2);
                s[nf][0] += b0.x; s[nf][1] += b0.y;
                s[nf][2] += b1.x; s[nf][3] += b1.y;
            }
        }
        #pragma unroll
        for (int nf = 0; nf < 8; nf++) {
            mx0 = fmaxf(mx0, fmaxf(s[nf][0], s[nf][1]));
            mx1 = fmaxf(mx1, fmaxf(s[nf][2], s[nf][3]));
        }
        mx0 = fmaxf(mx0, __shfl_xor_sync(0xFFFFFFFFu, mx0, 1));
        mx0 = fmaxf(mx0, __shfl_xor_sync(0xFFFFFFFFu, mx0, 2));
        mx1 = fmaxf(mx1, __shfl_xor_sync(0xFFFFFFFFu, mx1, 1));
        mx1 = fmaxf(mx1, __shfl_xor_sync(0xFFFFFFFFu, mx1, 2));

        float nm0 = fmaxf(m0, mx0), nm1 = fmaxf(m1, mx1);
        float c0f = __expf(m0 - nm0), c1f = __expf(m1 - nm1);
        l0 *= c0f; l1 *= c1f; m0 = nm0; m1 = nm1;
        #pragma unroll
        for (int nf = 0; nf < 8; nf++) {
            o[nf][0] *= c0f; o[nf][1] *= c0f; o[nf][2] *= c1f; o[nf][3] *= c1f;
        }
        uint32_t pfh[4][4], pfl[4][4];
        float la0 = 0.f, la1 = 0.f;
        #pragma unroll
        for (int nf = 0; nf < 8; nf++) {
            float p0 = __expf(s[nf][0] - nm0);
            float p1 = __expf(s[nf][1] - nm0);
            float p2 = __expf(s[nf][2] - nm1);
            float p3 = __expf(s[nf][3] - nm1);
            la0 += p0 + p1; la1 += p2 + p3;
            const int ks = nf >> 1;
            const int rbase = (nf & 1) * 2;
            split_pair_trunc(p0, p1, pfh[ks][rbase + 0], pfl[ks][rbase + 0]);
            split_pair_trunc(p2, p3, pfh[ks][rbase + 1], pfl[ks][rbase + 1]);
        }
        la0 += __shfl_xor_sync(0xFFFFFFFFu, la0, 1);
        la0 += __shfl_xor_sync(0xFFFFFFFFu, la0, 2);
        la1 += __shfl_xor_sync(0xFFFFFFFFu, la1, 1);
        la1 += __shfl_xor_sync(0xFFFFFFFFu, la1, 2);
        l0 += la0; l1 += la1;

        #pragma unroll
        for (int ks = 0; ks < 4; ks++) {
            #pragma unroll
            for (int p = 0; p < 4; p++) {
                const uint32_t off = lane_v + (uint32_t)(ks * 16 * VT + p * 16);
                uint32_t vh[4], vl[4];
                ldsm_x4_t(vh[0], vh[1], vh[2], vh[3], sb + 2 * (FL_VH + off));
                ldsm_x4_t(vl[0], vl[1], vl[2], vl[3], sb + 2 * (FL_VL + off));
                // Pair-interleaved: o[2p] / o[2p+1] alternate (spacing 2)
                mma_bf16(o[2 * p],     pfh[ks], vh);
                mma_bf16(o[2 * p + 1], pfh[ks], vh + 2);
                mma_bf16(o[2 * p],     pfl[ks], vh);
                mma_bf16(o[2 * p + 1], pfl[ks], vh + 2);
                mma_bf16(o[2 * p],     pfh[ks], vl);
                mma_bf16(o[2 * p + 1], pfh[ks], vl + 2);
            }
        }
        __syncthreads();
    }

    const float inv0 = 1.0f / l0, inv1 = 1.0f / l1;
    uint16_t* ohp0 = (uint16_t*)Oh + (size_t)(b * SEQ + qbase + wrow + g) * DMODEL + h * DEPTH;
    uint16_t* olp0 = (uint16_t*)Ol + (size_t)(b * SEQ + qbase + wrow + g) * DMODEL + h * DEPTH;
    uint16_t* ohp8 = ohp0 + (size_t)8 * DMODEL;
    uint16_t* olp8 = olp0 + (size_t)8 * DMODEL;
    #pragma unroll
    for (int nf = 0; nf < 8; nf++) {
        float v0 = o[nf][0] * inv0, v1 = o[nf][1] * inv0;
        float v2 = o[nf][2] * inv1, v3 = o[nf][3] * inv1;
        uint32_t h01, l01, h23, l23;
        split_pair_trunc(v0, v1, h01, l01);
        split_pair_trunc(v2, v3, h23, l23);
        const int col = nf * 8 + tig * 2;
        *(uint32_t*)(ohp0 + col) = h01;
        *(uint32_t*)(olp0 + col) = l01;
        *(uint32_t*)(ohp8 + col) = h23;
        *(uint32_t*)(olp8 + col) = l23;
    }
}

// ---------------------------------------------------------------------------
// Launch
// ---------------------------------------------------------------------------
extern "C" void kernel_launch(void* const* d_in, const int* in_sizes, int n_in,
                              void* d_out, int out_size)
{
    const float* x    = (const float*)d_in[0];
    const float* y    = (const float*)d_in[1];
    const float* bias = (const float*)d_in[2];
    const float* Wq   = (const float*)d_in[3];
    const float* Wk   = (const float*)d_in[4];
    const float* Wv   = (const float*)d_in[5];
    const float* Wo   = (const float*)d_in[6];
    float* out = (float*)d_out;

    __nv_bfloat16 *ah, *al, *yh, *yl, *qh, *ql, *kh, *kl, *vh, *vl;
    __nv_bfloat16 *wqh, *wql, *wkh, *wkl, *wvh, *wvl, *woh, *wol;
    cudaGetSymbolAddress((void**)&ah,  g_ah);
    cudaGetSymbolAddress((void**)&al,  g_al);
    cudaGetSymbolAddress((void**)&yh,  g_yh);
    cudaGetSymbolAddress((void**)&yl,  g_yl);
    cudaGetSymbolAddress((void**)&qh,  g_qh);
    cudaGetSymbolAddress((void**)&ql,  g_ql);
    cudaGetSymbolAddress((void**)&kh,  g_kh);
    cudaGetSymbolAddress((void**)&kl,  g_kl);
    cudaGetSymbolAddress((void**)&vh,  g_vh);
    cudaGetSymbolAddress((void**)&vl,  g_vl);
    cudaGetSymbolAddress((void**)&wqh, g_wqh);
    cudaGetSymbolAddress((void**)&wql, g_wql);
    cudaGetSymbolAddress((void**)&wkh, g_wkh);
    cudaGetSymbolAddress((void**)&wkl, g_wkl);
    cudaGetSymbolAddress((void**)&wvh, g_wvh);
    cudaGetSymbolAddress((void**)&wvl, g_wvl);
    cudaGetSymbolAddress((void**)&woh, g_woh);
    cudaGetSymbolAddress((void**)&wol, g_wol);

    cudaFuncSetAttribute(flash_bf16_kernel,
                         cudaFuncAttributeMaxDynamicSharedMemorySize, FLASH_SMEM_BYTES);
    cudaFuncSetAttribute(bf16_gemm_qkv,
                         cudaFuncAttributeMaxDynamicSharedMemorySize, GEMM_SMEM);
    cudaFuncSetAttribute(bf16_gemm_out,
                         cudaFuncAttributeMaxDynamicSharedMemorySize, GEMM_SMEM);

    // Bias zero-detection (fast path trigger; correct for any input)
    reset_flag_kernel<<<1, 1, 0, 0>>>();
    bias_check_kernel<<<512, 256, 0, 0>>>(bias, SEQ * SEQ / 4);

    // One batched elementwise split: x, y, and the 4 weights (stored [K][N])
    const int n4_xy = MROWS * DMODEL / 4;        // 1048576
    const int n4_w  = DMODEL * DMODEL / 4;       // 262144
    SplitBatch sb;
    sb.in[0] = x;  sb.oh[0] = ah;  sb.ol[0] = al;  sb.n4[0] = n4_xy;
    sb.in[1] = y;  sb.oh[1] = yh;  sb.ol[1] = yl;  sb.n4[1] = n4_xy;
    sb.in[2] = Wq; sb.oh[2] = wqh; sb.ol[2] = wql; sb.n4[2] = n4_w;
    sb.in[3] = Wk; sb.oh[3] = wkh; sb.ol[3] = wkl; sb.n4[3] = n4_w;
    sb.in[4] = Wv; sb.oh[4] = wvh; sb.ol[4] = wvl; sb.n4[4] = n4_w;
    sb.in[5] = Wo; sb.oh[5] = woh; sb.ol[5] = wol; sb.n4[5] = n4_w;
    dim3 sgrid((n4_xy + 255) / 256, 1, 6);
    split_kernel<<<sgrid, 256, 0, 0>>>(sb);

    // Batched q/k/v projections: one launch, grid.z = 3
    GemmBatch gb;
    gb.Ah[0] = ah; gb.Al[0] = al; gb.Bh[0] = wqh; gb.Bl[0] = wql;
    gb.Ch[0] = qh; gb.Cl[0] = ql; gb.alpha[0] = 8.0f;   // * sqrt(depth)
    gb.Ah[1] = yh; gb.Al[1] = yl; gb.Bh[1] = wkh; gb.Bl[1] = wkl;
    gb.Ch[1] = kh; gb.Cl[1] = kl; gb.alpha[1] = 1.0f;
    gb.Ah[2] = yh; gb.Al[2] = yl; gb.Bh[2] = wvh; gb.Bl[2] = wvl;
    gb.Ch[2] = vh; gb.Cl[2] = vl; gb.alpha[2] = 1.0f;

    dim3 qkvgrid(DMODEL / 128, MROWS / 128, 3);   // (8, 32, 3)
    bf16_gemm_qkv<<<qkvgrid, 256, GEMM_SMEM, 0>>>(gb);

    dim3 fgrid(SEQ / 128, NHEADS, BATCH);         // (16, 16, 2)
    flash_bf16_kernel<<<fgrid, 256, FLASH_SMEM_BYTES, 0>>>(
        qh, ql, kh, kl, vh, vl, bias, ah, al);

    dim3 ggrid(DMODEL / 128, MROWS / 128);        // (8, 32)
    bf16_gemm_out<<<ggrid, 256, GEMM_SMEM, 0>>>(ah, al, woh, wol, out);
}